// round 5
// baseline (speedup 1.0000x reference)
#include <cuda_runtime.h>

// Fused 3-layer GraphConv, B=524288.
//   A_ENC:  agg[j]  = sum_{i=4j-3..4j+2} x[i mod 40]
//   A_PRED: agg2[j] = z1[j] + w*(z1[j-1] + z1[j+1]),  w = exp(-1/9)
//   A_DEC:  out[4k]=s[k], out[4k+1]=out[4k+2]=s[k]+s[k+1], out[4k+3]=s[k+1]
//           where s[j] = dot(relu(pred(z1)[j]), dec_rel_w)
//
// R5: drop f32x2 entirely (R2/R4 showed packed-pair register bloat -> spills:
// 1.27GB DRAM traffic at cap 96). Scalar FFMA, R3 smem-z1 structure, rolling
// agg window, launch_bounds(128,5) -> 20 warps/SM with predicted ~88 regs.

#define WPRED 0.8948393168143698f

__global__ void __launch_bounds__(128, 5)
fused_gnn_kernel(const float* __restrict__ x,
                 const float* __restrict__ z,
                 const float* __restrict__ y,
                 const float* __restrict__ enc_rel_w,
                 const float* __restrict__ enc_rel_b,
                 const float* __restrict__ enc_root_w,
                 const float* __restrict__ pred_rel_w,
                 const float* __restrict__ pred_rel_b,
                 const float* __restrict__ pred_root_w,
                 const float* __restrict__ dec_rel_w,
                 const float* __restrict__ dec_rel_b,
                 const float* __restrict__ dec_root_w,
                 float* __restrict__ out,
                 long long B)
{
    // weights, scalar layout: W[f*8+g]
    __shared__ float wER[64], wPR[64], wPO[64];
    __shared__ float wErw[8], wErb[8], wPrb[8], wDrw[8];
    __shared__ float sDrb, sDrt;
    __shared__ __align__(16) float4 sbuf4[4][672];  // per-warp tile: 32 rows x 84 floats

    const int tid = threadIdx.x;
    if (tid < 64) {
        wER[tid] = enc_root_w[tid];
        wPR[tid] = pred_rel_w[tid];
        wPO[tid] = pred_root_w[tid];
    } else if (tid < 72) {
        int f = tid - 64;
        wErw[f] = enc_rel_w[f];
        wErb[f] = enc_rel_b[f];
        wPrb[f] = pred_rel_b[f];
        wDrw[f] = dec_rel_w[f];
    } else if (tid == 72) {
        sDrb = dec_rel_b[0]; sDrt = dec_root_w[0];
    }
    __syncthreads();

    const int warp = tid >> 5;
    const int lane = tid & 31;
    const long long e0 = ((long long)blockIdx.x * 4 + warp) * 32;
    if (e0 >= B) return;
    const int nval = (B - e0 >= 32) ? 32 : (int)(B - e0);
    float* buf = (float*)sbuf4[warp];

    // ===== stage x (coalesced, streaming), rows padded to 44 floats =====
    {
        const float4* xg = (const float4*)(x + e0 * 40);
        const int lim = nval * 10;
        #pragma unroll
        for (int k = 0; k < 10; k++) {
            int f4 = k * 32 + lane;
            if (f4 < lim) {
                float4 v = __ldcs(&xg[f4]);
                int e = f4 / 10, c = f4 % 10;
                *(float4*)&buf[e * 44 + c * 4] = v;
            }
        }
    }
    __syncwarp();

    // agg[j] = (last 3 of float4[j-1]) + (first 3 of float4[j]), rolling window
    float agg[10];
    if (lane < nval) {
        const float4* myx = (const float4*)&buf[lane * 44];
        float4 vp = myx[9];
        #pragma unroll
        for (int j = 0; j < 10; j++) {
            float4 v = myx[j];
            agg[j] = (vp.y + vp.z) + (vp.w + v.x) + (v.y + v.z);
            vp = v;
        }
    }
    __syncwarp();

    // ===== stage z (coalesced, streaming), rows padded to 84 floats =====
    {
        const float4* zg = (const float4*)(z + e0 * 80);
        const int lim = nval * 20;
        #pragma unroll
        for (int k = 0; k < 20; k++) {
            int f4 = k * 32 + lane;
            if (f4 < lim) {
                float4 v = __ldcs(&zg[f4]);
                int e = f4 / 20, c = f4 % 20;
                *(float4*)&buf[e * 84 + c * 4] = v;
            }
        }
    }
    __syncwarp();

    float s[10];
    if (lane < nval) {
        float* zrow = &buf[lane * 84];

        // ---- encoder: z1[j] overwrites z[j] in smem (thread-private row) ----
        #pragma unroll
        for (int j = 0; j < 10; j++) {
            float* r = zrow + j * 8;
            float4 za = *(const float4*)&r[0];
            float4 zb = *(const float4*)&r[4];
            float zg8[8] = {za.x, za.y, za.z, za.w, zb.x, zb.y, zb.z, zb.w};
            float t[8];
            #pragma unroll
            for (int f = 0; f < 8; f++) {
                float acc = fmaf(agg[j], wErw[f], wErb[f]);
                #pragma unroll
                for (int g = 0; g < 8; g++)
                    acc = fmaf(zg8[g], wER[f * 8 + g], acc);
                t[f] = fmaxf(acc, 0.0f);
            }
            *(float4*)&r[0] = make_float4(t[0], t[1], t[2], t[3]);
            *(float4*)&r[4] = make_float4(t[4], t[5], t[6], t[7]);
        }

        // ---- predictor + dec fold: rolling 3-row scalar window ----
        float zm[8], zc[8], zn[8];
        {
            float4 a = *(const float4*)&zrow[0];
            float4 b = *(const float4*)&zrow[4];
            zm[0]=a.x; zm[1]=a.y; zm[2]=a.z; zm[3]=a.w;
            zm[4]=b.x; zm[5]=b.y; zm[6]=b.z; zm[7]=b.w;
            a = *(const float4*)&zrow[8];
            b = *(const float4*)&zrow[12];
            zc[0]=a.x; zc[1]=a.y; zc[2]=a.z; zc[3]=a.w;
            zc[4]=b.x; zc[5]=b.y; zc[6]=b.z; zc[7]=b.w;
        }
        #pragma unroll
        for (int j = 1; j <= 8; j++) {
            float4 a = *(const float4*)&zrow[(j + 1) * 8];
            float4 b = *(const float4*)&zrow[(j + 1) * 8 + 4];
            zn[0]=a.x; zn[1]=a.y; zn[2]=a.z; zn[3]=a.w;
            zn[4]=b.x; zn[5]=b.y; zn[6]=b.z; zn[7]=b.w;
            float a2[8];
            #pragma unroll
            for (int g = 0; g < 8; g++)
                a2[g] = fmaf(WPRED, zm[g] + zn[g], zc[g]);
            float sj = 0.0f;
            #pragma unroll
            for (int f = 0; f < 8; f++) {
                float acc = wPrb[f];
                #pragma unroll
                for (int g = 0; g < 8; g++)
                    acc = fmaf(a2[g], wPR[f * 8 + g], acc);
                #pragma unroll
                for (int g = 0; g < 8; g++)
                    acc = fmaf(zc[g], wPO[f * 8 + g], acc);
                sj = fmaf(fmaxf(acc, 0.0f), wDrw[f], sj);
            }
            s[j] = sj;
            #pragma unroll
            for (int g = 0; g < 8; g++) { zm[g] = zc[g]; zc[g] = zn[g]; }
        }
        // zm=z1[8], zc=z1[9]; wrap rows reloaded from smem
        #pragma unroll
        for (int w2 = 0; w2 < 2; w2++) {   // w2=0 -> s[9] (nbr z1[0]); w2=1 -> s[0] (nbr z1[1])
            float4 a = *(const float4*)&zrow[w2 * 8];
            float4 b = *(const float4*)&zrow[w2 * 8 + 4];
            zn[0]=a.x; zn[1]=a.y; zn[2]=a.z; zn[3]=a.w;
            zn[4]=b.x; zn[5]=b.y; zn[6]=b.z; zn[7]=b.w;
            float a2[8];
            #pragma unroll
            for (int g = 0; g < 8; g++)
                a2[g] = fmaf(WPRED, zm[g] + zn[g], zc[g]);
            float sj = 0.0f;
            #pragma unroll
            for (int f = 0; f < 8; f++) {
                float acc = wPrb[f];
                #pragma unroll
                for (int g = 0; g < 8; g++)
                    acc = fmaf(a2[g], wPR[f * 8 + g], acc);
                #pragma unroll
                for (int g = 0; g < 8; g++)
                    acc = fmaf(zc[g], wPO[f * 8 + g], acc);
                sj = fmaf(fmaxf(acc, 0.0f), wDrw[f], sj);
            }
            s[(w2 == 0) ? 9 : 0] = sj;
            #pragma unroll
            for (int g = 0; g < 8; g++) { zm[g] = zc[g]; zc[g] = zn[g]; }
        }
    }
    __syncwarp();

    // ===== stage y (overwrites z region), compute out in place, store =====
    {
        const float4* yg = (const float4*)(y + e0 * 40);
        const int lim = nval * 10;
        #pragma unroll
        for (int k = 0; k < 10; k++) {
            int f4 = k * 32 + lane;
            if (f4 < lim) {
                float4 v = __ldcs(&yg[f4]);
                int e = f4 / 10, c = f4 % 10;
                *(float4*)&buf[e * 44 + c * 4] = v;
            }
        }
    }
    __syncwarp();

    if (lane < nval) {
        const float drb = sDrb, drt = sDrt;
        float4* myrow = (float4*)&buf[lane * 44];
        #pragma unroll
        for (int k = 0; k < 10; k++) {
            const int kp = (k + 1) % 10;
            const float c0 = s[k], c3 = s[kp];
            const float c12 = s[k] + s[kp];
            float4 v = myrow[k];
            v.x = fmaf(v.x, drt, drb) + c0;
            v.y = fmaf(v.y, drt, drb) + c12;
            v.z = fmaf(v.z, drt, drb) + c12;
            v.w = fmaf(v.w, drt, drb) + c3;
            myrow[k] = v;
        }
    }
    __syncwarp();

    {
        float4* og = (float4*)(out + e0 * 40);
        const int lim = nval * 10;
        #pragma unroll
        for (int k = 0; k < 10; k++) {
            int f4 = k * 32 + lane;
            if (f4 < lim) {
                int e = f4 / 10, c = f4 % 10;
                __stcs(&og[f4], *(const float4*)&buf[e * 44 + c * 4]);
            }
        }
    }
}

extern "C" void kernel_launch(void* const* d_in, const int* in_sizes, int n_in,
                              void* d_out, int out_size)
{
    const float* x          = (const float*)d_in[0];
    const float* z          = (const float*)d_in[1];
    const float* y          = (const float*)d_in[2];
    const float* enc_rel_w  = (const float*)d_in[3];
    const float* enc_rel_b  = (const float*)d_in[4];
    const float* enc_root_w = (const float*)d_in[5];
    const float* pred_rel_w = (const float*)d_in[6];
    const float* pred_rel_b = (const float*)d_in[7];
    const float* pred_root_w= (const float*)d_in[8];
    const float* dec_rel_w  = (const float*)d_in[9];
    const float* dec_rel_b  = (const float*)d_in[10];
    const float* dec_root_w = (const float*)d_in[11];

    const long long B = (long long)in_sizes[0] / 40;
    const int threads = 128;
    const long long elems_per_block = 128;
    const int blocks = (int)((B + elems_per_block - 1) / elems_per_block);

    fused_gnn_kernel<<<blocks, threads>>>(
        x, z, y, enc_rel_w, enc_rel_b, enc_root_w,
        pred_rel_w, pred_rel_b, pred_root_w,
        dec_rel_w, dec_rel_b, dec_root_w,
        (float*)d_out, B);
}